// round 12
// baseline (speedup 1.0000x reference)
#include <cuda_runtime.h>

#define NN 384
#define DD 128
#define MARGIN_F 0.2f
#define APB 4
#define NBLK (NN / APB)       // 96 blocks -> single wave
#define NTHR 768              // 24 warps, 6 per SMSP
#define MAXPOS 64
#define NWARP 24
#define TSMEM (NN * 32 * 16)  // 196608 B: full feat as float4[384][32]

// Scratch (no allocations allowed)
__device__ float g_total;
__device__ float g_count;
__device__ unsigned int g_ctr;

__device__ __forceinline__ int swz(int row, int c) {
    return row * 32 + (c ^ (row & 7));
}

__global__ void __launch_bounds__(NTHR) fused_k(
    const float* __restrict__ feat,
    const int*   __restrict__ y,
    float*       __restrict__ out)
{
    extern __shared__ float4 T4[];    // [row][c] swizzled, 384 x 32
    const int t = threadIdx.x;
    const int ab = blockIdx.x * APB;
    const int h = t / NN;             // k-half
    const int j = t - h * NN;         // column
    const int w = t >> 5, lane = t & 31;
    const unsigned FULL = 0xFFFFFFFFu;

    __shared__ float part[2][APB][NN];
    __shared__ float rrp[2][NN];
    __shared__ float ras[APB];
    __shared__ int   yas[APB];
    __shared__ float pos_d[APB][MAXPOS];
    __shared__ int   wc[APB][12];
    __shared__ int   wbase[APB][12];
    __shared__ int   np_s[APB];
    __shared__ float red_f[NWARP];

    // ---- stage ALL of feat into smem (swizzled float4) ----
    const float4* feat4 = reinterpret_cast<const float4*>(feat);
#pragma unroll
    for (int rep = 0; rep < 2; rep++) {
        float4 pre[8];
#pragma unroll
        for (int i = 0; i < 8; i++)
            pre[i] = feat4[(rep * 8 + i) * NTHR + t];
#pragma unroll
        for (int i = 0; i < 8; i++) {
            const int f = (rep * 8 + i) * NTHR + t;
            T4[swz(f >> 5, f & 31)] = pre[i];
        }
    }
    if (t < APB) yas[t] = y[ab + t];
    const int yj = __ldg(&y[j]);
    __syncthreads();

    // ---- dot phase: half h covers k4 = h*16 .. h*16+15 ----
    {
        float d0 = 0.f, d1 = 0.f, d2v = 0.f, d3 = 0.f, rr = 0.f;
        const int rbase = j * 32, rx = j & 7;
        const int a0b = (ab + 0) * 32, a0x = (ab + 0) & 7;
        const int a1b = (ab + 1) * 32, a1x = (ab + 1) & 7;
        const int a2b = (ab + 2) * 32, a2x = (ab + 2) & 7;
        const int a3b = (ab + 3) * 32, a3x = (ab + 3) & 7;
#pragma unroll
        for (int kk = 0; kk < 16; kk++) {
            const int c = h * 16 + kk;
            const float4 v = T4[rbase + (c ^ rx)];
            float4 a;
            a = T4[a0b + (c ^ a0x)];
            d0 += a.x * v.x; d0 += a.y * v.y; d0 += a.z * v.z; d0 += a.w * v.w;
            a = T4[a1b + (c ^ a1x)];
            d1 += a.x * v.x; d1 += a.y * v.y; d1 += a.z * v.z; d1 += a.w * v.w;
            a = T4[a2b + (c ^ a2x)];
            d2v += a.x * v.x; d2v += a.y * v.y; d2v += a.z * v.z; d2v += a.w * v.w;
            a = T4[a3b + (c ^ a3x)];
            d3 += a.x * v.x; d3 += a.y * v.y; d3 += a.z * v.z; d3 += a.w * v.w;
            rr += v.x * v.x; rr += v.y * v.y; rr += v.z * v.z; rr += v.w * v.w;
        }
        part[h][0][j] = d0; part[h][1][j] = d1;
        part[h][2][j] = d2v; part[h][3][j] = d3;
        rrp[h][j] = rr;
    }
    __syncthreads();

    // ---- combine partials; publish anchor norms ----
    float dts[APB], rr2;
#pragma unroll
    for (int m = 0; m < APB; m++)
        dts[m] = part[0][m][j] + part[1][m][j];
    rr2 = rrp[0][j] + rrp[1][j];
    if (h == 0 && (unsigned)(j - ab) < APB) ras[j - ab] = rr2;
    __syncthreads();

    // ---- d2 + ballot compaction (warps 0..11 only) ----
    float d2[APB];
    bool  isp[APB];
#pragma unroll
    for (int m = 0; m < APB; m++) {
        d2[m] = fmaxf(ras[m] + rr2 - 2.0f * dts[m], 0.0f);
        isp[m] = (yj == yas[m]) && (j != ab + m);
    }
    unsigned pm[APB];
    if (w < 12) {
#pragma unroll
        for (int m = 0; m < APB; m++) {
            pm[m] = __ballot_sync(FULL, isp[m]);
            if (lane == 0) wc[m][w] = __popc(pm[m]);
        }
    }
    __syncthreads();
    if (t < APB) {
        int s = 0;
#pragma unroll
        for (int ww = 0; ww < 12; ww++) { wbase[t][ww] = s; s += wc[t][ww]; }
        np_s[t] = s;
    }
    __syncthreads();
    if (w < 12) {
#pragma unroll
        for (int m = 0; m < APB; m++) {
            if (isp[m]) {
                const int idx = wbase[m][w] + __popc(pm[m] & ((1u << lane) - 1u));
                pos_d[m][idx] = d2[m] + MARGIN_F;
            }
        }
    }
    __syncthreads();

    // ---- triplet sums: i-loop split across halves ----
    float acc = 0.0f;
#pragma unroll
    for (int m = 0; m < APB; m++) {
        const int npm = np_s[m];
        if (yj != yas[m]) {
            const float dn = d2[m];
            for (int i = h; i < npm; i += 2) {
                const float v = pos_d[m][i] - dn;
                acc += (v > 0.0f) ? v : 0.0f;
            }
        }
    }

    // ---- reduce + global accumulate + last-block finalize ----
#pragma unroll
    for (int off = 16; off > 0; off >>= 1)
        acc += __shfl_down_sync(FULL, acc, off);
    if (lane == 0) red_f[w] = acc;
    __syncthreads();
    if (w == 0) {
        float af = (lane < NWARP) ? red_f[lane] : 0.0f;
#pragma unroll
        for (int off = 16; off > 0; off >>= 1)
            af += __shfl_down_sync(FULL, af, off);
        if (lane == 0) {
            int cnt = 0;
#pragma unroll
            for (int m = 0; m < APB; m++)
                cnt += np_s[m] * (NN - 1 - np_s[m]);
            atomicAdd(&g_total, af);
            atomicAdd(&g_count, (float)cnt);
            __threadfence();
            const unsigned done = atomicAdd(&g_ctr, 1u);
            if (done == NBLK - 1) {
                const float tot = atomicAdd(&g_total, 0.0f);
                const float cn  = atomicAdd(&g_count, 0.0f);
                out[0] = tot / cn;
                g_total = 0.0f;
                g_count = 0.0f;
                g_ctr   = 0u;
            }
        }
    }
}

extern "C" void kernel_launch(void* const* d_in, const int* in_sizes, int n_in,
                              void* d_out, int out_size) {
    const float* feat = (const float*)d_in[0];
    // d_in[1] = logits (unused by the loss)
    const int*   yv   = (const int*)d_in[2];
    float* out = (float*)d_out;

    static int attr_set = 0;
    if (!attr_set) {
        cudaFuncSetAttribute(fused_k, cudaFuncAttributeMaxDynamicSharedMemorySize,
                             TSMEM);
        attr_set = 1;
    }
    fused_k<<<NBLK, NTHR, TSMEM>>>(feat, yv, out);
}

// round 13
// speedup vs baseline: 1.0226x; 1.0226x over previous
#include <cuda_runtime.h>

#define NN 384
#define DD 128
#define MARGIN_F 0.2f
#define APB 4
#define NBLK (NN / APB)       // 96 blocks -> single wave
#define NTHR 768              // 24 warps, 6 per SMSP
#define MAXPOS 64
#define NWARP 24
#define TROW 33               // padded float4 row stride
#define TSMEM (NN * TROW * 16)  // 202752 B

// Scratch (no allocations allowed)
__device__ float g_total;
__device__ float g_count;
__device__ unsigned int g_ctr;

__global__ void __launch_bounds__(NTHR) fused_k(
    const float* __restrict__ feat,
    const int*   __restrict__ y,
    float*       __restrict__ out)
{
    extern __shared__ float4 T4[];    // [row][c] padded, 384 x 33
    const int t = threadIdx.x;
    const int ab = blockIdx.x * APB;
    const int h = t / NN;             // k-half
    const int j = t - h * NN;         // column
    const int w = t >> 5, lane = t & 31;
    const unsigned FULL = 0xFFFFFFFFu;

    __shared__ float4 fa4[APB][DD / 4];   // anchor rows (uniform reads)
    __shared__ float part[2][APB][NN];
    __shared__ float rrp[2][NN];
    __shared__ float ras[APB];
    __shared__ int   yas[APB];
    __shared__ float pos_d[APB][MAXPOS];
    __shared__ int   wc[APB][12];
    __shared__ int   wbase[APB][12];
    __shared__ int   np_s[APB];
    __shared__ float red_f[NWARP];

    // ---- stage ALL of feat into padded smem + anchor rows ----
    const float4* feat4 = reinterpret_cast<const float4*>(feat);
#pragma unroll
    for (int rep = 0; rep < 2; rep++) {
        float4 pre[8];
#pragma unroll
        for (int i = 0; i < 8; i++)
            pre[i] = feat4[(rep * 8 + i) * NTHR + t];
#pragma unroll
        for (int i = 0; i < 8; i++) {
            const int f = (rep * 8 + i) * NTHR + t;
            T4[(f >> 5) * TROW + (f & 31)] = pre[i];
        }
    }
    if (t < APB * (DD / 4)) {
        const int m = t >> 5, k4 = t & 31;
        fa4[m][k4] = feat4[(ab + m) * (DD / 4) + k4];
    }
    if (t < APB) yas[t] = y[ab + t];
    const int yj = __ldg(&y[j]);
    __syncthreads();

    // ---- dot phase: half h covers c = h*16 .. h*16+15 ----
    {
        float d0 = 0.f, d1 = 0.f, d2v = 0.f, d3 = 0.f, rr = 0.f;
        const float4* vrow = &T4[j * TROW + h * 16];
        const float4* a0p = &fa4[0][h * 16];
        const float4* a1p = &fa4[1][h * 16];
        const float4* a2p = &fa4[2][h * 16];
        const float4* a3p = &fa4[3][h * 16];
#pragma unroll
        for (int kk = 0; kk < 16; kk++) {
            const float4 v = vrow[kk];
            float4 a;
            a = a0p[kk];
            d0 += a.x * v.x; d0 += a.y * v.y; d0 += a.z * v.z; d0 += a.w * v.w;
            a = a1p[kk];
            d1 += a.x * v.x; d1 += a.y * v.y; d1 += a.z * v.z; d1 += a.w * v.w;
            a = a2p[kk];
            d2v += a.x * v.x; d2v += a.y * v.y; d2v += a.z * v.z; d2v += a.w * v.w;
            a = a3p[kk];
            d3 += a.x * v.x; d3 += a.y * v.y; d3 += a.z * v.z; d3 += a.w * v.w;
            rr += v.x * v.x; rr += v.y * v.y; rr += v.z * v.z; rr += v.w * v.w;
        }
        part[h][0][j] = d0; part[h][1][j] = d1;
        part[h][2][j] = d2v; part[h][3][j] = d3;
        rrp[h][j] = rr;
    }
    __syncthreads();

    // ---- combine partials; publish anchor norms ----
    float dts[APB], rr2;
#pragma unroll
    for (int m = 0; m < APB; m++)
        dts[m] = part[0][m][j] + part[1][m][j];
    rr2 = rrp[0][j] + rrp[1][j];
    if (h == 0 && (unsigned)(j - ab) < APB) ras[j - ab] = rr2;
    __syncthreads();

    // ---- d2 + ballot compaction (warps 0..11 carry columns uniquely) ----
    float d2[APB];
    bool  isp[APB];
#pragma unroll
    for (int m = 0; m < APB; m++) {
        d2[m] = fmaxf(ras[m] + rr2 - 2.0f * dts[m], 0.0f);
        isp[m] = (yj == yas[m]) && (j != ab + m);
    }
    unsigned pm[APB];
    if (w < 12) {
#pragma unroll
        for (int m = 0; m < APB; m++) {
            pm[m] = __ballot_sync(FULL, isp[m]);
            if (lane == 0) wc[m][w] = __popc(pm[m]);
        }
    }
    __syncthreads();
    if (t < APB) {
        int s = 0;
#pragma unroll
        for (int ww = 0; ww < 12; ww++) { wbase[t][ww] = s; s += wc[t][ww]; }
        np_s[t] = s;
    }
    __syncthreads();
    if (w < 12) {
#pragma unroll
        for (int m = 0; m < APB; m++) {
            if (isp[m]) {
                const int idx = wbase[m][w] + __popc(pm[m] & ((1u << lane) - 1u));
                pos_d[m][idx] = d2[m] + MARGIN_F;
            }
        }
    }
    __syncthreads();

    // ---- triplet sums: i-loop split across halves ----
    float acc = 0.0f;
#pragma unroll
    for (int m = 0; m < APB; m++) {
        const int npm = np_s[m];
        if (yj != yas[m]) {
            const float dn = d2[m];
            for (int i = h; i < npm; i += 2) {
                const float v = pos_d[m][i] - dn;
                acc += (v > 0.0f) ? v : 0.0f;
            }
        }
    }

    // ---- reduce + global accumulate + last-block finalize ----
#pragma unroll
    for (int off = 16; off > 0; off >>= 1)
        acc += __shfl_down_sync(FULL, acc, off);
    if (lane == 0) red_f[w] = acc;
    __syncthreads();
    if (w == 0) {
        float af = (lane < NWARP) ? red_f[lane] : 0.0f;
#pragma unroll
        for (int off = 16; off > 0; off >>= 1)
            af += __shfl_down_sync(FULL, af, off);
        if (lane == 0) {
            int cnt = 0;
#pragma unroll
            for (int m = 0; m < APB; m++)
                cnt += np_s[m] * (NN - 1 - np_s[m]);
            atomicAdd(&g_total, af);
            atomicAdd(&g_count, (float)cnt);
            __threadfence();
            const unsigned done = atomicAdd(&g_ctr, 1u);
            if (done == NBLK - 1) {
                const float tot = atomicAdd(&g_total, 0.0f);
                const float cn  = atomicAdd(&g_count, 0.0f);
                out[0] = tot / cn;
                g_total = 0.0f;
                g_count = 0.0f;
                g_ctr   = 0u;
            }
        }
    }
}

extern "C" void kernel_launch(void* const* d_in, const int* in_sizes, int n_in,
                              void* d_out, int out_size) {
    const float* feat = (const float*)d_in[0];
    // d_in[1] = logits (unused by the loss)
    const int*   yv   = (const int*)d_in[2];
    float* out = (float*)d_out;

    static int attr_set = 0;
    if (!attr_set) {
        cudaFuncSetAttribute(fused_k, cudaFuncAttributeMaxDynamicSharedMemorySize,
                             TSMEM);
        attr_set = 1;
    }
    fused_k<<<NBLK, NTHR, TSMEM>>>(feat, yv, out);
}